// round 1
// baseline (speedup 1.0000x reference)
#include <cuda_runtime.h>
#include <stdint.h>

// Problem constants (fixed by the reference setup)
#define Bb 4
#define Nn 2048
#define Cc 1024
#define Hh 16
#define Dh 64
#define KK 1024        // GEMM K dim (= C)

// Scratch (device globals: no allocation allowed in kernel_launch)
__device__ float g_q[Bb * Hh * Nn * Dh];   // [b][h][n][d]
__device__ float g_k[Bb * Hh * Nn * Dh];
__device__ float g_v[Bb * Hh * Nn * Dh];
__device__ float g_ao[Bb * Nn * Cc];       // attention output, [b][n][h*Dh+d]

// ---------------------------------------------------------------------------
// SGEMM: C[M,Ncols] = A[M,1024] * B[1024,Ncols] + bias, 128x128x8 tiles,
// 8x8 micro-tile per thread (256 threads). EPI=0: scatter into q/k/v.
// EPI=1: A is g_ao, plain write to Cout.
// ---------------------------------------------------------------------------
template <int EPI>
__global__ __launch_bounds__(256, 2) void sgemm128(
    const float* __restrict__ A, const float* __restrict__ Bm,
    const float* __restrict__ bias, float* __restrict__ Cout, int Ncols)
{
    __shared__ float As[8][128];   // [k][m] (transposed on store)
    __shared__ float Bs[8][128];   // [k][n]

    const int tid = threadIdx.x;
    const int tx = tid & 15;       // 16 cols of threads
    const int ty = tid >> 4;       // 16 rows of threads
    const int rowBase = blockIdx.y * 128;
    const int colBase = blockIdx.x * 128;

    const float* Aeff = (EPI == 1) ? (const float*)g_ao : A;

    // Global load mapping
    const int aRow = tid >> 1;           // 0..127
    const int aCol = (tid & 1) * 4;      // 0 or 4
    const int bRow = tid >> 5;           // 0..7
    const int bCol = (tid & 31) * 4;     // 0..124
    const float* Ap = Aeff + (rowBase + aRow) * KK + aCol;
    const float* Bp = Bm + bRow * Ncols + colBase + bCol;

    float acc[8][8];
#pragma unroll
    for (int i = 0; i < 8; i++)
#pragma unroll
        for (int j = 0; j < 8; j++) acc[i][j] = 0.f;

    float4 av = *(const float4*)Ap;
    float4 bv = *(const float4*)Bp;

    for (int k0 = 0; k0 < KK; k0 += 8) {
        __syncthreads();
        As[aCol + 0][aRow] = av.x;
        As[aCol + 1][aRow] = av.y;
        As[aCol + 2][aRow] = av.z;
        As[aCol + 3][aRow] = av.w;
        *(float4*)&Bs[bRow][bCol] = bv;
        __syncthreads();
        Ap += 8;
        Bp += 8 * Ncols;
        if (k0 + 8 < KK) {           // prefetch next tile under compute
            av = *(const float4*)Ap;
            bv = *(const float4*)Bp;
        }
#pragma unroll
        for (int kk = 0; kk < 8; kk++) {
            float4 a0 = *(const float4*)&As[kk][ty * 4];
            float4 a1 = *(const float4*)&As[kk][64 + ty * 4];
            float4 b0 = *(const float4*)&Bs[kk][tx * 4];
            float4 b1 = *(const float4*)&Bs[kk][64 + tx * 4];
            float ar[8] = {a0.x, a0.y, a0.z, a0.w, a1.x, a1.y, a1.z, a1.w};
            float br[8] = {b0.x, b0.y, b0.z, b0.w, b1.x, b1.y, b1.z, b1.w};
#pragma unroll
            for (int i = 0; i < 8; i++)
#pragma unroll
                for (int j = 0; j < 8; j++)
                    acc[i][j] = fmaf(ar[i], br[j], acc[i][j]);
        }
    }

    // Epilogue
#pragma unroll
    for (int i = 0; i < 8; i++) {
        const int row = rowBase + ((i < 4) ? (ty * 4 + i) : (64 + ty * 4 + (i - 4)));
#pragma unroll
        for (int half = 0; half < 2; half++) {
            const int col0 = colBase + half * 64 + tx * 4;
            float4 b4 = *(const float4*)&bias[col0];
            float4 o;
            o.x = acc[i][half * 4 + 0] + b4.x;
            o.y = acc[i][half * 4 + 1] + b4.y;
            o.z = acc[i][half * 4 + 2] + b4.z;
            o.w = acc[i][half * 4 + 3] + b4.w;
            if (EPI == 0) {
                // col -> (which, h, d); row -> (b, n). All power-of-2 splits.
                const int which = col0 >> 10;
                const int rem = col0 & 1023;
                const int hh = rem >> 6;
                const int dd = rem & 63;
                const int bb = row >> 11;
                const int nn = row & 2047;
                float* dst = (which == 0) ? g_q : (which == 1) ? g_k : g_v;
                *(float4*)&dst[(((bb * Hh + hh) * Nn + nn) << 6) + dd] = o;
            } else {
                *(float4*)&Cout[row * Ncols + col0] = o;
            }
        }
    }
}

// ---------------------------------------------------------------------------
// Flash attention (fp32, online softmax). One block per (64-query tile, h, b).
// 64-key tiles streamed. Q,K stored d-major with pitch 68 (conflict-free),
// V key-major pitch 68, scores pitch 68.
// ---------------------------------------------------------------------------
#define SP 68                       // smem pitch (floats)
#define SMEM_ATTN_BYTES (4 * 64 * SP * 4 + 3 * 64 * 4 + 64)

__global__ __launch_bounds__(256) void attn_kernel(const uint8_t* __restrict__ mask)
{
    extern __shared__ float sm[];
    float* Qt = sm;                  // [d][q]   64 x SP
    float* Kt = Qt + 64 * SP;        // [d][key] 64 x SP
    float* Vs = Kt + 64 * SP;        // [key][d] 64 x SP
    float* Ss = Vs + 64 * SP;        // [q][key] 64 x SP
    float* m_row = Ss + 64 * SP;     // [64]
    float* l_row = m_row + 64;       // [64]
    float* a_row = l_row + 64;       // [64]
    uint8_t* maskS = (uint8_t*)(a_row + 64);

    const int tid = threadIdx.x;
    const int tx = tid & 15;
    const int ty = tid >> 4;
    const int qb = blockIdx.x;
    const int h = blockIdx.y;
    const int b = blockIdx.z;

    const float* qp = g_q + ((b * Hh + h) * Nn + qb * 64) * Dh;
    const float* kb = g_k + ((b * Hh + h) * Nn) * Dh;
    const float* vb = g_v + ((b * Hh + h) * Nn) * Dh;
    const uint8_t* mrow = mask + b * Nn;

    const float scale = 0.125f;      // Dh^-0.5, folded into Q

    // Load Q transposed+scaled. key-major lane mapping -> conflict-free stores.
#pragma unroll
    for (int it = 0; it < 4; it++) {
        int idx = tid + it * 256;
        int q = idx & 63;
        int d4 = (idx >> 6) << 2;
        float4 v = *(const float4*)(qp + q * Dh + d4);
        Qt[(d4 + 0) * SP + q] = v.x * scale;
        Qt[(d4 + 1) * SP + q] = v.y * scale;
        Qt[(d4 + 2) * SP + q] = v.z * scale;
        Qt[(d4 + 3) * SP + q] = v.w * scale;
    }
    if (tid < 64) { m_row[tid] = -1e30f; l_row[tid] = 0.f; }

    float oacc[4][4];
#pragma unroll
    for (int i = 0; i < 4; i++)
#pragma unroll
        for (int j = 0; j < 4; j++) oacc[i][j] = 0.f;

    for (int kt = 0; kt < Nn / 64; kt++) {
        __syncthreads();             // prev-iter P*V reads done before overwrite
        const float* kp = kb + kt * 64 * Dh;
        const float* vp = vb + kt * 64 * Dh;
#pragma unroll
        for (int it = 0; it < 4; it++) {
            int idx = tid + it * 256;
            int key = idx & 63;
            int d4 = (idx >> 6) << 2;
            float4 kv = *(const float4*)(kp + key * Dh + d4);
            Kt[(d4 + 0) * SP + key] = kv.x;
            Kt[(d4 + 1) * SP + key] = kv.y;
            Kt[(d4 + 2) * SP + key] = kv.z;
            Kt[(d4 + 3) * SP + key] = kv.w;
            int vkey = idx >> 4;
            int vd4 = (idx & 15) << 2;
            float4 vv = *(const float4*)(vp + vkey * Dh + vd4);
            *(float4*)&Vs[vkey * SP + vd4] = vv;
        }
        if (tid < 64) maskS[tid] = mrow[kt * 64 + tid];
        __syncthreads();

        // S = (Q*scale) K^T : 4x4 micro-tile, rows ty*4.., cols tx*4..
        float sacc[4][4];
#pragma unroll
        for (int i = 0; i < 4; i++)
#pragma unroll
            for (int j = 0; j < 4; j++) sacc[i][j] = 0.f;
#pragma unroll 8
        for (int d = 0; d < Dh; d++) {
            float4 a = *(const float4*)&Qt[d * SP + ty * 4];
            float4 q4 = *(const float4*)&Kt[d * SP + tx * 4];
            sacc[0][0] = fmaf(a.x, q4.x, sacc[0][0]);
            sacc[0][1] = fmaf(a.x, q4.y, sacc[0][1]);
            sacc[0][2] = fmaf(a.x, q4.z, sacc[0][2]);
            sacc[0][3] = fmaf(a.x, q4.w, sacc[0][3]);
            sacc[1][0] = fmaf(a.y, q4.x, sacc[1][0]);
            sacc[1][1] = fmaf(a.y, q4.y, sacc[1][1]);
            sacc[1][2] = fmaf(a.y, q4.z, sacc[1][2]);
            sacc[1][3] = fmaf(a.y, q4.w, sacc[1][3]);
            sacc[2][0] = fmaf(a.z, q4.x, sacc[2][0]);
            sacc[2][1] = fmaf(a.z, q4.y, sacc[2][1]);
            sacc[2][2] = fmaf(a.z, q4.z, sacc[2][2]);
            sacc[2][3] = fmaf(a.z, q4.w, sacc[2][3]);
            sacc[3][0] = fmaf(a.w, q4.x, sacc[3][0]);
            sacc[3][1] = fmaf(a.w, q4.y, sacc[3][1]);
            sacc[3][2] = fmaf(a.w, q4.z, sacc[3][2]);
            sacc[3][3] = fmaf(a.w, q4.w, sacc[3][3]);
        }
#pragma unroll
        for (int i = 0; i < 4; i++) {
            float4 s4;
            s4.x = sacc[i][0]; s4.y = sacc[i][1]; s4.z = sacc[i][2]; s4.w = sacc[i][3];
            *(float4*)&Ss[(ty * 4 + i) * SP + tx * 4] = s4;
        }
        __syncthreads();

        // Online softmax: 4 lanes per query row, shfl-reduce within quads.
        {
            const int r = tid >> 2;
            const int seg = tid & 3;
            float* srow = Ss + r * SP + seg * 16;
            const uint8_t* mp = maskS + seg * 16;
            float vals[16];
            float tmax = -1e30f;
#pragma unroll
            for (int c = 0; c < 16; c++) {
                float v = srow[c];
                if (mp[c]) v = -1e30f;
                vals[c] = v;
                tmax = fmaxf(tmax, v);
            }
            tmax = fmaxf(tmax, __shfl_xor_sync(0xffffffffu, tmax, 1));
            tmax = fmaxf(tmax, __shfl_xor_sync(0xffffffffu, tmax, 2));
            const float mo = m_row[r];
            const float mn = fmaxf(mo, tmax);
            float ls = 0.f;
#pragma unroll
            for (int c = 0; c < 16; c++) {
                float p = __expf(vals[c] - mn);
                srow[c] = p;
                ls += p;
            }
            ls += __shfl_xor_sync(0xffffffffu, ls, 1);
            ls += __shfl_xor_sync(0xffffffffu, ls, 2);
            if (seg == 0) {
                float al = __expf(mo - mn);
                a_row[r] = al;
                l_row[r] = al * l_row[r] + ls;
                m_row[r] = mn;
            }
        }
        __syncthreads();

        // O = alpha*O + P*V
        const float al0 = a_row[ty * 4 + 0];
        const float al1 = a_row[ty * 4 + 1];
        const float al2 = a_row[ty * 4 + 2];
        const float al3 = a_row[ty * 4 + 3];
#pragma unroll
        for (int j = 0; j < 4; j++) {
            oacc[0][j] *= al0;
            oacc[1][j] *= al1;
            oacc[2][j] *= al2;
            oacc[3][j] *= al3;
        }
#pragma unroll 4
        for (int key = 0; key < 64; key++) {
            float p0 = Ss[(ty * 4 + 0) * SP + key];
            float p1 = Ss[(ty * 4 + 1) * SP + key];
            float p2 = Ss[(ty * 4 + 2) * SP + key];
            float p3 = Ss[(ty * 4 + 3) * SP + key];
            float4 vv = *(const float4*)&Vs[key * SP + tx * 4];
            oacc[0][0] = fmaf(p0, vv.x, oacc[0][0]);
            oacc[0][1] = fmaf(p0, vv.y, oacc[0][1]);
            oacc[0][2] = fmaf(p0, vv.z, oacc[0][2]);
            oacc[0][3] = fmaf(p0, vv.w, oacc[0][3]);
            oacc[1][0] = fmaf(p1, vv.x, oacc[1][0]);
            oacc[1][1] = fmaf(p1, vv.y, oacc[1][1]);
            oacc[1][2] = fmaf(p1, vv.z, oacc[1][2]);
            oacc[1][3] = fmaf(p1, vv.w, oacc[1][3]);
            oacc[2][0] = fmaf(p2, vv.x, oacc[2][0]);
            oacc[2][1] = fmaf(p2, vv.y, oacc[2][1]);
            oacc[2][2] = fmaf(p2, vv.z, oacc[2][2]);
            oacc[2][3] = fmaf(p2, vv.w, oacc[2][3]);
            oacc[3][0] = fmaf(p3, vv.x, oacc[3][0]);
            oacc[3][1] = fmaf(p3, vv.y, oacc[3][1]);
            oacc[3][2] = fmaf(p3, vv.z, oacc[3][2]);
            oacc[3][3] = fmaf(p3, vv.w, oacc[3][3]);
        }
    }

    // Normalize and write to [b][n][h*Dh + d]  (l_row synced inside last iter)
#pragma unroll
    for (int i = 0; i < 4; i++) {
        const int n = qb * 64 + ty * 4 + i;
        const float invl = 1.f / l_row[ty * 4 + i];
        float4 o;
        o.x = oacc[i][0] * invl;
        o.y = oacc[i][1] * invl;
        o.z = oacc[i][2] * invl;
        o.w = oacc[i][3] * invl;
        *(float4*)&g_ao[(b * Nn + n) * Cc + h * Dh + tx * 4] = o;
    }
}

// ---------------------------------------------------------------------------
extern "C" void kernel_launch(void* const* d_in, const int* in_sizes, int n_in,
                              void* d_out, int out_size)
{
    (void)in_sizes; (void)n_in; (void)out_size;
    const float* x      = (const float*)d_in[0];
    const uint8_t* mask = (const uint8_t*)d_in[1];  // all-False in this problem
    const float* Wqkv   = (const float*)d_in[2];
    const float* bqkv   = (const float*)d_in[3];
    const float* Wproj  = (const float*)d_in[4];
    const float* bproj  = (const float*)d_in[5];
    float* out = (float*)d_out;

    // 1) QKV projection, scattered into [B,H,N,Dh] q/k/v
    sgemm128<0><<<dim3((3 * Cc) / 128, (Bb * Nn) / 128), 256>>>(
        x, Wqkv, bqkv, nullptr, 3 * Cc);

    // 2) Flash attention
    cudaFuncSetAttribute(attn_kernel, cudaFuncAttributeMaxDynamicSharedMemorySize,
                         SMEM_ATTN_BYTES);
    attn_kernel<<<dim3(Nn / 64, Hh, Bb), 256, SMEM_ATTN_BYTES>>>(mask);

    // 3) Output projection (A = g_ao inside the kernel for EPI=1)
    sgemm128<1><<<dim3(Cc / 128, (Bb * Nn) / 128), 256>>>(
        nullptr, Wproj, bproj, out, Cc);
}

// round 2
// speedup vs baseline: 1.1797x; 1.1797x over previous
#include <cuda_runtime.h>
#include <stdint.h>

#define Bb 4
#define Nn 2048
#define Cc 1024
#define Hh 16
#define Dh 64
#define KK 1024

// Scratch
__device__ float g_q[Bb * Hh * Nn * Dh];   // [b][h][n][d]
__device__ float g_k[Bb * Hh * Nn * Dh];
__device__ float g_v[Bb * Hh * Nn * Dh];
__device__ float g_ao[Bb * Nn * Cc];       // [b][n][h*Dh+d]

// ---------------- packed f32x2 helpers ----------------
__device__ __forceinline__ unsigned long long ffma2(unsigned long long a,
                                                    unsigned long long b,
                                                    unsigned long long c) {
    unsigned long long d;
    asm("fma.rn.f32x2 %0, %1, %2, %3;" : "=l"(d) : "l"(a), "l"(b), "l"(c));
    return d;
}
__device__ __forceinline__ unsigned long long mul2(unsigned long long a,
                                                   unsigned long long b) {
    unsigned long long d;
    asm("mul.rn.f32x2 %0, %1, %2;" : "=l"(d) : "l"(a), "l"(b));
    return d;
}
__device__ __forceinline__ unsigned long long dup2(float x) {
    unsigned xi = __float_as_uint(x);
    unsigned long long d;
    asm("mov.b64 %0, {%1, %1};" : "=l"(d) : "r"(xi));
    return d;
}
__device__ __forceinline__ float2 unpk2(unsigned long long v) {
    unsigned lo, hi;
    asm("mov.b64 {%0, %1}, %2;" : "=r"(lo), "=r"(hi) : "l"(v));
    return make_float2(__uint_as_float(lo), __uint_as_float(hi));
}
__device__ __forceinline__ void cpa16(void* smem_ptr, const void* gptr) {
    unsigned sa = (unsigned)__cvta_generic_to_shared(smem_ptr);
    asm volatile("cp.async.cg.shared.global [%0], [%1], 16;" :: "r"(sa), "l"(gptr));
}
__device__ __forceinline__ void cpa_commit() {
    asm volatile("cp.async.commit_group;" ::: "memory");
}
__device__ __forceinline__ void cpa_wait0() {
    asm volatile("cp.async.wait_group 0;" ::: "memory");
}

// ---------------------------------------------------------------------------
// SGEMM 128x128x8, 8x8 micro-tile, FFMA2 inner loop.
// ---------------------------------------------------------------------------
template <int EPI>
__global__ __launch_bounds__(256, 2) void sgemm128(
    const float* __restrict__ A, const float* __restrict__ Bm,
    const float* __restrict__ bias, float* __restrict__ Cout, int Ncols)
{
    __shared__ float As[8][128];
    __shared__ float Bs[8][128];

    const int tid = threadIdx.x;
    const int tx = tid & 15;
    const int ty = tid >> 4;
    const int rowBase = blockIdx.y * 128;
    const int colBase = blockIdx.x * 128;

    const float* Aeff = (EPI == 1) ? (const float*)g_ao : A;

    const int aRow = tid >> 1;
    const int aCol = (tid & 1) * 4;
    const int bRow = tid >> 5;
    const int bCol = (tid & 31) * 4;
    const float* Ap = Aeff + (rowBase + aRow) * KK + aCol;
    const float* Bp = Bm + bRow * Ncols + colBase + bCol;

    unsigned long long acc2[8][4];
#pragma unroll
    for (int i = 0; i < 8; i++)
#pragma unroll
        for (int j = 0; j < 4; j++) acc2[i][j] = 0ULL;

    float4 av = *(const float4*)Ap;
    float4 bv = *(const float4*)Bp;

    for (int k0 = 0; k0 < KK; k0 += 8) {
        __syncthreads();
        As[aCol + 0][aRow] = av.x;
        As[aCol + 1][aRow] = av.y;
        As[aCol + 2][aRow] = av.z;
        As[aCol + 3][aRow] = av.w;
        *(float4*)&Bs[bRow][bCol] = bv;
        __syncthreads();
        Ap += 8;
        Bp += 8 * Ncols;
        if (k0 + 8 < KK) {
            av = *(const float4*)Ap;
            bv = *(const float4*)Bp;
        }
#pragma unroll
        for (int kk = 0; kk < 8; kk++) {
            float4 a0 = *(const float4*)&As[kk][ty * 4];
            float4 a1 = *(const float4*)&As[kk][64 + ty * 4];
            ulonglong2 b0 = *(const ulonglong2*)&Bs[kk][tx * 4];
            ulonglong2 b1 = *(const ulonglong2*)&Bs[kk][64 + tx * 4];
            unsigned long long br[4] = {b0.x, b0.y, b1.x, b1.y};
            float ar[8] = {a0.x, a0.y, a0.z, a0.w, a1.x, a1.y, a1.z, a1.w};
#pragma unroll
            for (int i = 0; i < 8; i++) {
                unsigned long long ad = dup2(ar[i]);
#pragma unroll
                for (int j = 0; j < 4; j++)
                    acc2[i][j] = ffma2(ad, br[j], acc2[i][j]);
            }
        }
    }

#pragma unroll
    for (int i = 0; i < 8; i++) {
        const int row = rowBase + ((i < 4) ? (ty * 4 + i) : (64 + ty * 4 + (i - 4)));
#pragma unroll
        for (int half = 0; half < 2; half++) {
            const int col0 = colBase + half * 64 + tx * 4;
            float4 b4 = *(const float4*)&bias[col0];
            float2 p0 = unpk2(acc2[i][half * 2 + 0]);
            float2 p1 = unpk2(acc2[i][half * 2 + 1]);
            float4 o;
            o.x = p0.x + b4.x;
            o.y = p0.y + b4.y;
            o.z = p1.x + b4.z;
            o.w = p1.y + b4.w;
            if (EPI == 0) {
                const int which = col0 >> 10;
                const int rem = col0 & 1023;
                const int hh = rem >> 6;
                const int dd = rem & 63;
                const int bb = row >> 11;
                const int nn = row & 2047;
                float* dst = (which == 0) ? g_q : (which == 1) ? g_k : g_v;
                *(float4*)&dst[(((bb * Hh + hh) * Nn + nn) << 6) + dd] = o;
            } else {
                *(float4*)&Cout[row * Ncols + col0] = o;
            }
        }
    }
}

// ---------------------------------------------------------------------------
// Flash attention: 128 queries x 128-key tiles, 8x8 micro-tiles (1.0 B/FMA)
// for BOTH S=QK^T and P*V. PV split into two 64-key groups, combined at end.
// ---------------------------------------------------------------------------
#define QP 132
#define VP 68
// smem layout (floats)
#define OFF_QS 0
#define OFF_KS (64 * QP)                 // 8448
#define OFF_VS (OFF_KS + 2 * 8 * QP)     // 10560
#define OFF_PS (OFF_VS + 128 * VP)       // 19264
#define OFF_AR (OFF_PS + 128 * QP)       // 36160
#define OFF_LR (OFF_AR + 128)            // 36288
#define OFF_MK (OFF_LR + 128)            // 36416
#define ATTN_SMEM_FLOATS (OFF_MK + 512)  // 36928
#define ATTN_SMEM_BYTES (ATTN_SMEM_FLOATS * 4)

__global__ __launch_bounds__(256, 1) void attn_kernel(const uint8_t* __restrict__ mask)
{
    extern __shared__ float sm[];
    float* Qs = sm + OFF_QS;             // [d 64][q 128] pitch QP
    float* Ks = sm + OFF_KS;             // [2][dd 8][key 128] pitch QP
    float* Vs = sm + OFF_VS;             // [key 128][d 64] pitch VP
    float* Ps = sm + OFF_PS;             // [key 128][q 128] pitch QP
    float* a_row = sm + OFF_AR;
    float* l_row = sm + OFF_LR;
    uint8_t* maskSm = (uint8_t*)(sm + OFF_MK);

    const int tid = threadIdx.x;
    const int tx = tid & 15;
    const int ty = tid >> 4;
    const int qb = blockIdx.x;
    const int h = blockIdx.y;
    const int b = blockIdx.z;

    const float* qp = g_q + ((b * Hh + h) * Nn + qb * 128) * Dh;
    const float* kb = g_k + ((b * Hh + h) * Nn) * Dh;
    const float* vb = g_v + ((b * Hh + h) * Nn) * Dh;

    // PV-phase mapping
    const int g = tid >> 7;              // key-group 0/1
    const int pt = tid & 127;
    const int ry = pt >> 3;              // 0..15 -> q rows ry*4.., 64+ry*4..
    const int rx = pt & 7;               // 0..7  -> d cols rx*8..rx*8+7

    // mask row (2048 bytes) once
    ((unsigned long long*)maskSm)[tid] =
        ((const unsigned long long*)(mask + b * Nn))[tid];

    // Q transposed + pre-scaled
#pragma unroll
    for (int it = 0; it < 8; it++) {
        int idx = tid + it * 256;
        int q = idx >> 4;
        int d4 = (idx & 15) << 2;
        float4 v = *(const float4*)(qp + q * Dh + d4);
        Qs[(d4 + 0) * QP + q] = v.x * 0.125f;
        Qs[(d4 + 1) * QP + q] = v.y * 0.125f;
        Qs[(d4 + 2) * QP + q] = v.z * 0.125f;
        Qs[(d4 + 3) * QP + q] = v.w * 0.125f;
    }

    float m_r[8], l_r[8];
#pragma unroll
    for (int i = 0; i < 8; i++) { m_r[i] = -1e30f; l_r[i] = 0.f; }
    unsigned long long o2[8][4];
#pragma unroll
    for (int i = 0; i < 8; i++)
#pragma unroll
        for (int j = 0; j < 4; j++) o2[i][j] = 0ULL;

    const int akey = tid >> 1;           // K-chunk load mapping
    const int ad4 = (tid & 1) << 2;

    for (int kt = 0; kt < Nn / 128; kt++) {
        __syncthreads();                 // prev PV done; Qs/mask ready on kt=0
        const float* kp = kb + kt * 128 * Dh;
        const float* vp = vb + kt * 128 * Dh;

        // async V tile -> Vs
#pragma unroll
        for (int it = 0; it < 8; it++) {
            int idx = tid + it * 256;
            int key = idx >> 4;
            int d4 = (idx & 15) << 2;
            cpa16(&Vs[key * VP + d4], vp + key * Dh + d4);
        }
        cpa_commit();

        // ---- S = Q K^T over 8 d-chunks, double-buffered K ----
        unsigned long long s2[8][4];
#pragma unroll
        for (int i = 0; i < 8; i++)
#pragma unroll
            for (int j = 0; j < 4; j++) s2[i][j] = 0ULL;

        {
            float4 k0 = *(const float4*)(kp + akey * Dh + ad4);
            float* kd = Ks;
            kd[(ad4 + 0) * QP + akey] = k0.x;
            kd[(ad4 + 1) * QP + akey] = k0.y;
            kd[(ad4 + 2) * QP + akey] = k0.z;
            kd[(ad4 + 3) * QP + akey] = k0.w;
        }
        __syncthreads();

        for (int c = 0; c < 8; c++) {
            float4 knext;
            if (c < 7)
                knext = *(const float4*)(kp + akey * Dh + (c + 1) * 8 + ad4);
            const float* kbuf = Ks + (c & 1) * (8 * QP);
#pragma unroll
            for (int dd = 0; dd < 8; dd++) {
                const float* qrow = Qs + (c * 8 + dd) * QP;
                const float* krow = kbuf + dd * QP;
                float4 a0 = *(const float4*)(qrow + ty * 4);
                float4 a1 = *(const float4*)(qrow + 64 + ty * 4);
                ulonglong2 b0 = *(const ulonglong2*)(krow + tx * 4);
                ulonglong2 b1 = *(const ulonglong2*)(krow + 64 + tx * 4);
                unsigned long long br[4] = {b0.x, b0.y, b1.x, b1.y};
                float ar[8] = {a0.x, a0.y, a0.z, a0.w, a1.x, a1.y, a1.z, a1.w};
#pragma unroll
                for (int i = 0; i < 8; i++) {
                    unsigned long long ad = dup2(ar[i]);
#pragma unroll
                    for (int j = 0; j < 4; j++)
                        s2[i][j] = ffma2(ad, br[j], s2[i][j]);
                }
            }
            if (c < 7) {
                float* kd = Ks + ((c + 1) & 1) * (8 * QP);
                kd[(ad4 + 0) * QP + akey] = knext.x;
                kd[(ad4 + 1) * QP + akey] = knext.y;
                kd[(ad4 + 2) * QP + akey] = knext.z;
                kd[(ad4 + 3) * QP + akey] = knext.w;
                __syncthreads();
            }
        }

        cpa_wait0();                     // V tile resident

        // ---- online softmax (stats replicated across 16 lanes per row) ----
        const uint8_t* mrow = maskSm + kt * 128;
        float alpha_v[8];
#pragma unroll
        for (int ih = 0; ih < 2; ih++) {
            float pv4[4][8];
#pragma unroll
            for (int ii = 0; ii < 4; ii++) {
                const int i = ih * 4 + ii;
                float v[8];
#pragma unroll
                for (int j2 = 0; j2 < 4; j2++) {
                    float2 u = unpk2(s2[i][j2]);
                    v[j2 * 2] = u.x;
                    v[j2 * 2 + 1] = u.y;
                }
#pragma unroll
                for (int j = 0; j < 8; j++) {
                    int key = (j < 4) ? tx * 4 + j : 64 + tx * 4 + (j - 4);
                    if (mrow[key]) v[j] = -1e30f;
                }
                float tm = v[0];
#pragma unroll
                for (int j = 1; j < 8; j++) tm = fmaxf(tm, v[j]);
                tm = fmaxf(tm, __shfl_xor_sync(0xffffffffu, tm, 1));
                tm = fmaxf(tm, __shfl_xor_sync(0xffffffffu, tm, 2));
                tm = fmaxf(tm, __shfl_xor_sync(0xffffffffu, tm, 4));
                tm = fmaxf(tm, __shfl_xor_sync(0xffffffffu, tm, 8));
                const float mn = fmaxf(m_r[i], tm);
                float s = 0.f;
#pragma unroll
                for (int j = 0; j < 8; j++) {
                    float p = __expf(v[j] - mn);
                    pv4[ii][j] = p;
                    s += p;
                }
                s += __shfl_xor_sync(0xffffffffu, s, 1);
                s += __shfl_xor_sync(0xffffffffu, s, 2);
                s += __shfl_xor_sync(0xffffffffu, s, 4);
                s += __shfl_xor_sync(0xffffffffu, s, 8);
                const float al = __expf(m_r[i] - mn);
                alpha_v[i] = al;
                l_r[i] = al * l_r[i] + s;
                m_r[i] = mn;
            }
            // P -> smem transposed [key][q]
#pragma unroll
            for (int j = 0; j < 8; j++) {
                int key = (j < 4) ? tx * 4 + j : 64 + tx * 4 + (j - 4);
                float4 o4 = make_float4(pv4[0][j], pv4[1][j], pv4[2][j], pv4[3][j]);
                *(float4*)&Ps[key * QP + ih * 64 + ty * 4] = o4;
            }
        }
        if (tx == 0) {
#pragma unroll
            for (int i = 0; i < 8; i++) {
                int r = (i < 4) ? ty * 4 + i : 64 + ty * 4 + (i - 4);
                a_row[r] = alpha_v[i];
                if (kt == Nn / 128 - 1) l_row[r] = l_r[i];
            }
        }
        __syncthreads();

        // ---- O = alpha*O + P*V (each group does 64 keys) ----
        float alph[8];
#pragma unroll
        for (int i = 0; i < 8; i++) {
            int r = (i < 4) ? ry * 4 + i : 64 + ry * 4 + (i - 4);
            alph[i] = a_row[r];
        }
#pragma unroll
        for (int i = 0; i < 8; i++) {
            unsigned long long ad = dup2(alph[i]);
#pragma unroll
            for (int j = 0; j < 4; j++) o2[i][j] = mul2(ad, o2[i][j]);
        }
#pragma unroll 8
        for (int kk = 0; kk < 64; kk++) {
            const int key = g * 64 + kk;
            float4 p0 = *(const float4*)&Ps[key * QP + ry * 4];
            float4 p1 = *(const float4*)&Ps[key * QP + 64 + ry * 4];
            ulonglong2 v0 = *(const ulonglong2*)&Vs[key * VP + rx * 8];
            ulonglong2 v1 = *(const ulonglong2*)&Vs[key * VP + rx * 8 + 4];
            unsigned long long vr[4] = {v0.x, v0.y, v1.x, v1.y};
            float pr[8] = {p0.x, p0.y, p0.z, p0.w, p1.x, p1.y, p1.z, p1.w};
#pragma unroll
            for (int i = 0; i < 8; i++) {
                unsigned long long pd = dup2(pr[i]);
#pragma unroll
                for (int j = 0; j < 4; j++)
                    o2[i][j] = ffma2(pd, vr[j], o2[i][j]);
            }
        }
    }

    // ---- combine the two key-groups, normalize, write out ----
    __syncthreads();
    if (g == 1) {
#pragma unroll
        for (int i = 0; i < 8; i++) {
            int r = (i < 4) ? ry * 4 + i : 64 + ry * 4 + (i - 4);
            float2 u0 = unpk2(o2[i][0]);
            float2 u1 = unpk2(o2[i][1]);
            float2 u2 = unpk2(o2[i][2]);
            float2 u3 = unpk2(o2[i][3]);
            *(float4*)&Ps[r * VP + rx * 8] = make_float4(u0.x, u0.y, u1.x, u1.y);
            *(float4*)&Ps[r * VP + rx * 8 + 4] = make_float4(u2.x, u2.y, u3.x, u3.y);
        }
    }
    __syncthreads();
    if (g == 0) {
#pragma unroll
        for (int i = 0; i < 8; i++) {
            int r = (i < 4) ? ry * 4 + i : 64 + ry * 4 + (i - 4);
            float invl = 1.f / l_row[r];
            float4 q0 = *(const float4*)&Ps[r * VP + rx * 8];
            float4 q1 = *(const float4*)&Ps[r * VP + rx * 8 + 4];
            float2 u0 = unpk2(o2[i][0]);
            float2 u1 = unpk2(o2[i][1]);
            float2 u2 = unpk2(o2[i][2]);
            float2 u3 = unpk2(o2[i][3]);
            float* dst = g_ao + (b * Nn + qb * 128 + r) * Cc + h * Dh + rx * 8;
            float4 w0, w1;
            w0.x = (u0.x + q0.x) * invl;
            w0.y = (u0.y + q0.y) * invl;
            w0.z = (u1.x + q0.z) * invl;
            w0.w = (u1.y + q0.w) * invl;
            w1.x = (u2.x + q1.x) * invl;
            w1.y = (u2.y + q1.y) * invl;
            w1.z = (u3.x + q1.z) * invl;
            w1.w = (u3.y + q1.w) * invl;
            *(float4*)dst = w0;
            *(float4*)(dst + 4) = w1;
        }
    }
}

// ---------------------------------------------------------------------------
extern "C" void kernel_launch(void* const* d_in, const int* in_sizes, int n_in,
                              void* d_out, int out_size)
{
    (void)in_sizes; (void)n_in; (void)out_size;
    const float* x      = (const float*)d_in[0];
    const uint8_t* mask = (const uint8_t*)d_in[1];
    const float* Wqkv   = (const float*)d_in[2];
    const float* bqkv   = (const float*)d_in[3];
    const float* Wproj  = (const float*)d_in[4];
    const float* bproj  = (const float*)d_in[5];
    float* out = (float*)d_out;

    sgemm128<0><<<dim3((3 * Cc) / 128, (Bb * Nn) / 128), 256>>>(
        x, Wqkv, bqkv, nullptr, 3 * Cc);

    cudaFuncSetAttribute(attn_kernel, cudaFuncAttributeMaxDynamicSharedMemorySize,
                         ATTN_SMEM_BYTES);
    attn_kernel<<<dim3(Nn / 128, Hh, Bb), 256, ATTN_SMEM_BYTES>>>(mask);

    sgemm128<1><<<dim3(Cc / 128, (Bb * Nn) / 128), 256>>>(
        nullptr, Wproj, bproj, out, Cc);
}

// round 5
// speedup vs baseline: 1.5049x; 1.2756x over previous
#include <cuda_runtime.h>
#include <cuda_bf16.h>
#include <stdint.h>

#define Bb 4
#define Nn 2048
#define Cc 1024
#define Hh 16
#define Dh 64
#define KK 1024

// Scratch (device globals)
__device__ float g_q[Bb * Hh * Nn * Dh];
__device__ float g_k[Bb * Hh * Nn * Dh];
__device__ float g_v[Bb * Hh * Nn * Dh];
__device__ float g_ao[Bb * Nn * Cc];
__device__ __nv_bfloat16 g_xhi[Bb * Nn * Cc];
__device__ __nv_bfloat16 g_xlo[Bb * Nn * Cc];
__device__ __nv_bfloat16 g_aohi[Bb * Nn * Cc];
__device__ __nv_bfloat16 g_aolo[Bb * Nn * Cc];
__device__ __nv_bfloat16 g_wqt_hi[3 * Cc * Cc];   // [3072][1024] K-major
__device__ __nv_bfloat16 g_wqt_lo[3 * Cc * Cc];
__device__ __nv_bfloat16 g_wpt_hi[Cc * Cc];       // [1024][1024] K-major
__device__ __nv_bfloat16 g_wpt_lo[Cc * Cc];

// ---------------- helpers ----------------
__device__ __forceinline__ unsigned long long ffma2(unsigned long long a,
                                                    unsigned long long b,
                                                    unsigned long long c) {
    unsigned long long d;
    asm("fma.rn.f32x2 %0, %1, %2, %3;" : "=l"(d) : "l"(a), "l"(b), "l"(c));
    return d;
}
__device__ __forceinline__ unsigned long long mul2(unsigned long long a,
                                                   unsigned long long b) {
    unsigned long long d;
    asm("mul.rn.f32x2 %0, %1, %2;" : "=l"(d) : "l"(a), "l"(b));
    return d;
}
__device__ __forceinline__ unsigned long long dup2(float x) {
    unsigned xi = __float_as_uint(x);
    unsigned long long d;
    asm("mov.b64 %0, {%1, %1};" : "=l"(d) : "r"(xi));
    return d;
}
__device__ __forceinline__ float2 unpk2(unsigned long long v) {
    unsigned lo, hi;
    asm("mov.b64 {%0, %1}, %2;" : "=r"(lo), "=r"(hi) : "l"(v));
    return make_float2(__uint_as_float(lo), __uint_as_float(hi));
}
__device__ __forceinline__ void cpa16(void* smem_ptr, const void* gptr) {
    unsigned sa = (unsigned)__cvta_generic_to_shared(smem_ptr);
    asm volatile("cp.async.cg.shared.global [%0], [%1], 16;" :: "r"(sa), "l"(gptr));
}
__device__ __forceinline__ void cpa16s(uint32_t sa, const void* gptr) {
    asm volatile("cp.async.cg.shared.global [%0], [%1], 16;" :: "r"(sa), "l"(gptr));
}
__device__ __forceinline__ void cpa_commit() {
    asm volatile("cp.async.commit_group;" ::: "memory");
}
__device__ __forceinline__ void cpa_wait0() {
    asm volatile("cp.async.wait_group 0;" ::: "memory");
}
__device__ __forceinline__ void cpa_wait1() {
    asm volatile("cp.async.wait_group 1;" ::: "memory");
}
__device__ __forceinline__ uint32_t s2u(const void* p) {
    uint32_t a;
    asm("{ .reg .u64 t; cvta.to.shared.u64 t, %1; cvt.u32.u64 %0, t; }"
        : "=r"(a) : "l"(p));
    return a;
}

#define LDSM4(r, addr) \
    asm volatile("ldmatrix.sync.aligned.m8n8.x4.shared.b16 {%0,%1,%2,%3}, [%4];" \
        : "=r"((r)[0]), "=r"((r)[1]), "=r"((r)[2]), "=r"((r)[3]) : "r"(addr))

#define MMA_BF16(d, a, b) \
    asm volatile("mma.sync.aligned.m16n8k16.row.col.f32.bf16.bf16.f32 " \
        "{%0,%1,%2,%3}, {%4,%5,%6,%7}, {%8,%9}, {%0,%1,%2,%3};" \
        : "+f"((d)[0]), "+f"((d)[1]), "+f"((d)[2]), "+f"((d)[3]) \
        : "r"((a)[0]), "r"((a)[1]), "r"((a)[2]), "r"((a)[3]), \
          "r"((b)[0]), "r"((b)[1]))

// ---------------------------------------------------------------------------
// Conversion kernels
// ---------------------------------------------------------------------------
struct bh4 { __nv_bfloat16 a, b, c, d; };

__global__ void split_bf16(const float4* __restrict__ src,
                           __nv_bfloat16* __restrict__ hi,
                           __nv_bfloat16* __restrict__ lo) {
    int i = blockIdx.x * 256 + threadIdx.x;
    float4 v = src[i];
    __nv_bfloat16 hx = __float2bfloat16(v.x);
    __nv_bfloat16 hy = __float2bfloat16(v.y);
    __nv_bfloat16 hz = __float2bfloat16(v.z);
    __nv_bfloat16 hw = __float2bfloat16(v.w);
    bh4 h = {hx, hy, hz, hw};
    bh4 l = {__float2bfloat16(v.x - __bfloat162float(hx)),
             __float2bfloat16(v.y - __bfloat162float(hy)),
             __float2bfloat16(v.z - __bfloat162float(hz)),
             __float2bfloat16(v.w - __bfloat162float(hw))};
    *(bh4*)(hi + 4 * i) = h;
    *(bh4*)(lo + 4 * i) = l;
}

// W[K][N] row-major -> Wt[N][K] bf16 hi/lo
__global__ void transpose_split(const float* __restrict__ W,
                                __nv_bfloat16* __restrict__ hi,
                                __nv_bfloat16* __restrict__ lo,
                                int K, int N) {
    __shared__ float t[32][33];
    const int n0 = blockIdx.x * 32, k0 = blockIdx.y * 32;
    const int tx = threadIdx.x, ty = threadIdx.y;
#pragma unroll
    for (int i = 0; i < 4; i++)
        t[ty + 8 * i][tx] = W[(k0 + ty + 8 * i) * N + n0 + tx];
    __syncthreads();
#pragma unroll
    for (int i = 0; i < 4; i++) {
        float v = t[tx][ty + 8 * i];
        __nv_bfloat16 h = __float2bfloat16(v);
        __nv_bfloat16 l = __float2bfloat16(v - __bfloat162float(h));
        int o = (n0 + ty + 8 * i) * K + k0 + tx;
        hi[o] = h;
        lo[o] = l;
    }
}

// ---------------------------------------------------------------------------
// mma.sync bf16 3-term GEMM: C = Ahi*Bhi + Ahi*Blo + Alo*Bhi (+bias)
// A: [M][1024] K-major bf16, B: [Ncols][1024] K-major bf16 (pre-transposed).
// CTA: 128x128 tile, 8 warps (4 M x 2 N), warp tile 32x64.
// K chunks of 32, 2-stage cp.async double buffer.
// ---------------------------------------------------------------------------
#define CH 32
#define PITB 80                    // smem row pitch in bytes (40 bf16)
#define TILE_B (128 * PITB)        // 10240
#define STAGE_B (4 * TILE_B)       // 40960
#define GEMM_SMEM (2 * STAGE_B)    // 81920

template <int EPI>
__global__ __launch_bounds__(256, 1) void mma_gemm(
    const __nv_bfloat16* __restrict__ Ahi, const __nv_bfloat16* __restrict__ Alo,
    const __nv_bfloat16* __restrict__ Bhi, const __nv_bfloat16* __restrict__ Blo,
    const float* __restrict__ bias, float* __restrict__ Cout, int Ncols)
{
    extern __shared__ __align__(128) char smem[];
    const uint32_t sb = s2u(smem);
    const int tid = threadIdx.x;
    const int wid = tid >> 5, lane = tid & 31;
    const int warpM = wid & 3, warpN = wid >> 2;
    const int rowBase = blockIdx.y * 128;
    const int colBase = blockIdx.x * 128;

    const __nv_bfloat16* Ah = Ahi + rowBase * KK;
    const __nv_bfloat16* Al = Alo + rowBase * KK;
    const __nv_bfloat16* Bh = Bhi + colBase * KK;
    const __nv_bfloat16* Bl = Blo + colBase * KK;

    float acc[2][8][4];
#pragma unroll
    for (int i = 0; i < 2; i++)
#pragma unroll
        for (int j = 0; j < 8; j++)
#pragma unroll
            for (int q = 0; q < 4; q++) acc[i][j][q] = 0.f;

    // ldmatrix base offsets (bytes) within a tile
    const uint32_t aOff =
        (uint32_t)((warpM * 32 + (lane & 15)) * PITB + (lane >> 4) * 16);
    const uint32_t bOff =
        (uint32_t)((warpN * 64 + ((lane >> 4) << 3) + (lane & 7)) * PITB +
                   ((lane >> 3) & 1) * 16);

    // global load mapping: 512 x 16B per tile; idx -> (row, quarter)
    const int r0 = tid >> 2, q0 = (tid & 3);
    const int r1 = (tid + 256) >> 2, q1 = ((tid + 256) & 3);

#define LOADC(c)                                                               \
    {                                                                          \
        const uint32_t st_ = sb + ((c) & 1) * STAGE_B;                         \
        const int k0_ = (c) * CH;                                              \
        {                                                                      \
            const uint32_t doff = (uint32_t)(r0 * PITB + q0 * 16);             \
            const int gs = r0 * KK + k0_ + q0 * 8;                             \
            cpa16s(st_ + doff, Ah + gs);                                       \
            cpa16s(st_ + TILE_B + doff, Al + gs);                              \
            cpa16s(st_ + 2 * TILE_B + doff, Bh + gs);                          \
            cpa16s(st_ + 3 * TILE_B + doff, Bl + gs);                          \
        }                                                                      \
        {                                                                      \
            const uint32_t doff = (uint32_t)(r1 * PITB + q1 * 16);             \
            const int gs = r1 * KK + k0_ + q1 * 8;                             \
            cpa16s(st_ + doff, Ah + gs);                                       \
            cpa16s(st_ + TILE_B + doff, Al + gs);                              \
            cpa16s(st_ + 2 * TILE_B + doff, Bh + gs);                          \
            cpa16s(st_ + 3 * TILE_B + doff, Bl + gs);                          \
        }                                                                      \
        cpa_commit();                                                          \
    }

    LOADC(0);

    for (int c = 0; c < KK / CH; c++) {
        if (c + 1 < KK / CH) {
            LOADC(c + 1);
            cpa_wait1();
        } else {
            cpa_wait0();
        }
        __syncthreads();

        const uint32_t st = sb + (c & 1) * STAGE_B;
#pragma unroll
        for (int ks = 0; ks < 2; ks++) {
            uint32_t ah[2][4], al[2][4];
#pragma unroll
            for (int mt = 0; mt < 2; mt++) {
                const uint32_t addr = st + aOff + mt * (16 * PITB) + ks * 32;
                LDSM4(ah[mt], addr);
                LDSM4(al[mt], addr + TILE_B);
            }
            uint32_t bh[4][4], bl[4][4];
#pragma unroll
            for (int nt = 0; nt < 4; nt++) {
                const uint32_t addr =
                    st + 2 * TILE_B + bOff + nt * (16 * PITB) + ks * 32;
                LDSM4(bh[nt], addr);
                LDSM4(bl[nt], addr + TILE_B);
            }
#pragma unroll
            for (int mt = 0; mt < 2; mt++)
#pragma unroll
                for (int nt = 0; nt < 4; nt++)
#pragma unroll
                    for (int sub = 0; sub < 2; sub++) {
                        const int n8 = nt * 2 + sub;
                        MMA_BF16(acc[mt][n8], ah[mt], (&bh[nt][sub * 2]));
                        MMA_BF16(acc[mt][n8], ah[mt], (&bl[nt][sub * 2]));
                        MMA_BF16(acc[mt][n8], al[mt], (&bh[nt][sub * 2]));
                    }
        }
        __syncthreads();
    }
#undef LOADC

    // Epilogue: per (mt, n8): rows rowT, rowT+8; cols col0, col0+1.
#pragma unroll
    for (int mt = 0; mt < 2; mt++) {
        const int rowT = rowBase + warpM * 32 + mt * 16 + (lane >> 2);
#pragma unroll
        for (int n8 = 0; n8 < 8; n8++) {
            const int col0 = colBase + warpN * 64 + n8 * 8 + (lane & 3) * 2;
            const float2 b2 = *(const float2*)&bias[col0];
            float2 vlo = make_float2(acc[mt][n8][0] + b2.x, acc[mt][n8][1] + b2.y);
            float2 vhi = make_float2(acc[mt][n8][2] + b2.x, acc[mt][n8][3] + b2.y);
            if (EPI == 0) {
                const int which = col0 >> 10;
                const int hh = (col0 & 1023) >> 6;
                const int dd = col0 & 63;
                float* base = (which == 0) ? g_q : (which == 1) ? g_k : g_v;
                const int bb = rowT >> 11;
                const int nn = rowT & 2047;
                *(float2*)&base[(((bb * Hh + hh) * Nn + nn) << 6) + dd] = vlo;
                const int rw2 = rowT + 8;
                const int bb2 = rw2 >> 11;
                const int nn2 = rw2 & 2047;
                *(float2*)&base[(((bb2 * Hh + hh) * Nn + nn2) << 6) + dd] = vhi;
            } else {
                *(float2*)&Cout[rowT * Ncols + col0] = vlo;
                *(float2*)&Cout[(rowT + 8) * Ncols + col0] = vhi;
            }
        }
    }
}

// ---------------------------------------------------------------------------
// Flash attention (fp32, identical to round-2 passing version)
// ---------------------------------------------------------------------------
#define QP 132
#define VP 68
#define OFF_QS 0
#define OFF_KS (64 * QP)
#define OFF_VS (OFF_KS + 2 * 8 * QP)
#define OFF_PS (OFF_VS + 128 * VP)
#define OFF_AR (OFF_PS + 128 * QP)
#define OFF_LR (OFF_AR + 128)
#define OFF_MK (OFF_LR + 128)
#define ATTN_SMEM_FLOATS (OFF_MK + 512)
#define ATTN_SMEM_BYTES (ATTN_SMEM_FLOATS * 4)

__global__ __launch_bounds__(256, 1) void attn_kernel(const uint8_t* __restrict__ mask)
{
    extern __shared__ float sm[];
    float* Qs = sm + OFF_QS;
    float* Ks = sm + OFF_KS;
    float* Vs = sm + OFF_VS;
    float* Ps = sm + OFF_PS;
    float* a_row = sm + OFF_AR;
    float* l_row = sm + OFF_LR;
    uint8_t* maskSm = (uint8_t*)(sm + OFF_MK);

    const int tid = threadIdx.x;
    const int tx = tid & 15;
    const int ty = tid >> 4;
    const int qb = blockIdx.x;
    const int h = blockIdx.y;
    const int b = blockIdx.z;

    const float* qp = g_q + ((b * Hh + h) * Nn + qb * 128) * Dh;
    const float* kb = g_k + ((b * Hh + h) * Nn) * Dh;
    const float* vb = g_v + ((b * Hh + h) * Nn) * Dh;

    const int g = tid >> 7;
    const int pt = tid & 127;
    const int ry = pt >> 3;
    const int rx = pt & 7;

    ((unsigned long long*)maskSm)[tid] =
        ((const unsigned long long*)(mask + b * Nn))[tid];

#pragma unroll
    for (int it = 0; it < 8; it++) {
        int idx = tid + it * 256;
        int q = idx >> 4;
        int d4 = (idx & 15) << 2;
        float4 v = *(const float4*)(qp + q * Dh + d4);
        Qs[(d4 + 0) * QP + q] = v.x * 0.125f;
        Qs[(d4 + 1) * QP + q] = v.y * 0.125f;
        Qs[(d4 + 2) * QP + q] = v.z * 0.125f;
        Qs[(d4 + 3) * QP + q] = v.w * 0.125f;
    }

    float m_r[8], l_r[8];
#pragma unroll
    for (int i = 0; i < 8; i++) { m_r[i] = -1e30f; l_r[i] = 0.f; }
    unsigned long long o2[8][4];
#pragma unroll
    for (int i = 0; i < 8; i++)
#pragma unroll
        for (int j = 0; j < 4; j++) o2[i][j] = 0ULL;

    const int akey = tid >> 1;
    const int ad4 = (tid & 1) << 2;

    for (int kt = 0; kt < Nn / 128; kt++) {
        __syncthreads();
        const float* kp = kb + kt * 128 * Dh;
        const float* vp = vb + kt * 128 * Dh;

#pragma unroll
        for (int it = 0; it < 8; it++) {
            int idx = tid + it * 256;
            int key = idx >> 4;
            int d4 = (idx & 15) << 2;
            cpa16(&Vs[key * VP + d4], vp + key * Dh + d4);
        }
        cpa_commit();

        unsigned long long s2[8][4];
#pragma unroll
        for (int i = 0; i < 8; i++)
#pragma unroll
            for (int j = 0; j < 4; j++) s2[i][j] = 0ULL;

        {
            float4 k0 = *(const float4*)(kp + akey * Dh + ad4);
            float* kd = Ks;
            kd[(ad4 + 0) * QP + akey] = k0.x;
            kd[(ad4 + 1) * QP + akey] = k0.y;
            kd[(ad4 + 2) * QP + akey] = k0.z;
            kd[(ad4 + 3) * QP + akey] = k0.w;
        }
        __syncthreads();

        for (int c = 0; c < 8; c++) {
            float4 knext;
            if (c < 7)
                knext = *(const float4*)(kp + akey * Dh + (c + 1) * 8 + ad4);
            const float* kbuf = Ks + (c & 1) * (8 * QP);
#pragma unroll
            for (int dd = 0; dd < 8; dd++) {
                const float* qrow = Qs + (c * 8 + dd) * QP;
                const float* krow = kbuf + dd * QP;
                float4 a0 = *(const float4*)(qrow + ty * 4);
                float4 a1 = *(const float4*)(qrow + 64 + ty * 4);
                ulonglong2 b0 = *(const ulonglong2*)(krow + tx * 4);
                ulonglong2 b1 = *(const ulonglong2*)(krow + 64 + tx * 4);
                unsigned long long br[4] = {b0.x, b0.y, b1.x, b1.y};
                float ar[8] = {a0.x, a0.y, a0.z, a0.w, a1.x, a1.y, a1.z, a1.w};
#pragma unroll
                for (int i = 0; i < 8; i++) {
                    unsigned long long ad = dup2(ar[i]);
#pragma unroll
                    for (int j = 0; j < 4; j++)
                        s2[i][j] = ffma2(ad, br[j], s2[i][j]);
                }
            }
            if (c < 7) {
                float* kd = Ks + ((c + 1) & 1) * (8 * QP);
                kd[(ad4 + 0) * QP + akey] = knext.x;
                kd[(ad4 + 1) * QP + akey] = knext.y;
                kd[(ad4 + 2) * QP + akey] = knext.z;
                kd[(ad4 + 3) * QP + akey] = knext.w;
                __syncthreads();
            }
        }

        cpa_wait0();

        const uint8_t* mrow = maskSm + kt * 128;
        float alpha_v[8];
#pragma unroll
        for (int ih = 0; ih < 2; ih++) {
            float pv4[4][8];
#pragma unroll
            for (int ii = 0; ii < 4; ii++) {
                const int i = ih * 4 + ii;
                float v[8];
#pragma unroll
                for (int j2 = 0; j2 < 4; j2++) {
                    float2 u = unpk2(s2[i][j2]);
                    v[j2 * 2] = u.x;
                    v[j2 * 2 + 1] = u.y;
                }
#pragma unroll
                for (int j = 0; j < 8; j++) {
                    int key = (j < 4) ? tx * 4 + j : 64 + tx * 4 + (j - 4);
                    if (mrow[key]) v[j] = -1e30f;
                }
                float tm = v[0];
#pragma unroll
                for (int j = 1; j < 8; j++) tm = fmaxf(tm, v[j]);
                tm = fmaxf(tm, __shfl_xor_sync(0xffffffffu, tm, 1));
                tm = fmaxf(tm, __shfl_xor_sync(0xffffffffu, tm, 2));
                tm = fmaxf(tm, __shfl_xor_sync(0xffffffffu, tm, 4));
                tm = fmaxf(tm, __shfl_xor_sync(0xffffffffu, tm, 8));
                const float mn = fmaxf(m_r[i], tm);
                float s = 0.f;
#pragma unroll
                for (int j = 0; j < 8; j++) {
                    float p = __expf(v[j] - mn);
                    pv4[ii][j] = p;
                    s += p;
                }
                s += __shfl_xor_sync(0xffffffffu, s, 1);
                s += __shfl_xor_sync(0xffffffffu, s, 2);
                s += __shfl_xor_sync(0xffffffffu, s, 4);
                s += __shfl_xor_sync(0xffffffffu, s, 8);
                const float al = __expf(m_r[i] - mn);
                alpha_v[i] = al;
                l_r[i] = al * l_r[i] + s;
                m_r[i] = mn;
            }
#pragma unroll
            for (int j = 0; j < 8; j++) {
                int key = (j < 4) ? tx * 4 + j : 64 + tx * 4 + (j - 4);
                float4 o4 = make_float4(pv4[0][j], pv4[1][j], pv4[2][j], pv4[3][j]);
                *(float4*)&Ps[key * QP + ih * 64 + ty * 4] = o4;
            }
        }
        if (tx == 0) {
#pragma unroll
            for (int i = 0; i < 8; i++) {
                int r = (i < 4) ? ty * 4 + i : 64 + ty * 4 + (i - 4);
                a_row[r] = alpha_v[i];
                if (kt == Nn / 128 - 1) l_row[r] = l_r[i];
            }
        }
        __syncthreads();

        float alph[8];
#pragma unroll
        for (int i = 0; i < 8; i++) {
            int r = (i < 4) ? ry * 4 + i : 64 + ry * 4 + (i - 4);
            alph[i] = a_row[r];
        }
#pragma unroll
        for (int i = 0; i < 8; i++) {
            unsigned long long ad = dup2(alph[i]);
#pragma unroll
            for (int j = 0; j < 4; j++) o2[i][j] = mul2(ad, o2[i][j]);
        }
#pragma unroll 8
        for (int kk = 0; kk < 64; kk++) {
            const int key = g * 64 + kk;
            float4 p0 = *(const float4*)&Ps[key * QP + ry * 4];
            float4 p1 = *(const float4*)&Ps[key * QP + 64 + ry * 4];
            ulonglong2 v0 = *(const ulonglong2*)&Vs[key * VP + rx * 8];
            ulonglong2 v1 = *(const ulonglong2*)&Vs[key * VP + rx * 8 + 4];
            unsigned long long vr[4] = {v0.x, v0.y, v1.x, v1.y};
            float pr[8] = {p0.x, p0.y, p0.z, p0.w, p1.x, p1.y, p1.z, p1.w};
#pragma unroll
            for (int i = 0; i < 8; i++) {
                unsigned long long pd = dup2(pr[i]);
#pragma unroll
                for (int j = 0; j < 4; j++)
                    o2[i][j] = ffma2(pd, vr[j], o2[i][j]);
            }
        }
    }

    __syncthreads();
    if (g == 1) {
#pragma unroll
        for (int i = 0; i < 8; i++) {
            int r = (i < 4) ? ry * 4 + i : 64 + ry * 4 + (i - 4);
            float2 u0 = unpk2(o2[i][0]);
            float2 u1 = unpk2(o2[i][1]);
            float2 u2 = unpk2(o2[i][2]);
            float2 u3 = unpk2(o2[i][3]);
            *(float4*)&Ps[r * VP + rx * 8] = make_float4(u0.x, u0.y, u1.x, u1.y);
            *(float4*)&Ps[r * VP + rx * 8 + 4] = make_float4(u2.x, u2.y, u3.x, u3.y);
        }
    }
    __syncthreads();
    if (g == 0) {
#pragma unroll
        for (int i = 0; i < 8; i++) {
            int r = (i < 4) ? ry * 4 + i : 64 + ry * 4 + (i - 4);
            float invl = 1.f / l_row[r];
            float4 q0 = *(const float4*)&Ps[r * VP + rx * 8];
            float4 q1 = *(const float4*)&Ps[r * VP + rx * 8 + 4];
            float2 u0 = unpk2(o2[i][0]);
            float2 u1 = unpk2(o2[i][1]);
            float2 u2 = unpk2(o2[i][2]);
            float2 u3 = unpk2(o2[i][3]);
            float* dst = g_ao + (b * Nn + qb * 128 + r) * Cc + h * Dh + rx * 8;
            float4 w0, w1;
            w0.x = (u0.x + q0.x) * invl;
            w0.y = (u0.y + q0.y) * invl;
            w0.z = (u1.x + q0.z) * invl;
            w0.w = (u1.y + q0.w) * invl;
            w1.x = (u2.x + q1.x) * invl;
            w1.y = (u2.y + q1.y) * invl;
            w1.z = (u3.x + q1.z) * invl;
            w1.w = (u3.y + q1.w) * invl;
            *(float4*)dst = w0;
            *(float4*)(dst + 4) = w1;
        }
    }
}

// ---------------------------------------------------------------------------
extern "C" void kernel_launch(void* const* d_in, const int* in_sizes, int n_in,
                              void* d_out, int out_size)
{
    (void)in_sizes; (void)n_in; (void)out_size;
    const float* x      = (const float*)d_in[0];
    const uint8_t* mask = (const uint8_t*)d_in[1];
    const float* Wqkv   = (const float*)d_in[2];
    const float* bqkv   = (const float*)d_in[3];
    const float* Wproj  = (const float*)d_in[4];
    const float* bproj  = (const float*)d_in[5];
    float* out = (float*)d_out;

    __nv_bfloat16 *xhi, *xlo, *aohi, *aolo, *wqh, *wql, *wph, *wpl;
    float *gao;
    cudaGetSymbolAddress((void**)&xhi, g_xhi);
    cudaGetSymbolAddress((void**)&xlo, g_xlo);
    cudaGetSymbolAddress((void**)&aohi, g_aohi);
    cudaGetSymbolAddress((void**)&aolo, g_aolo);
    cudaGetSymbolAddress((void**)&wqh, g_wqt_hi);
    cudaGetSymbolAddress((void**)&wql, g_wqt_lo);
    cudaGetSymbolAddress((void**)&wph, g_wpt_hi);
    cudaGetSymbolAddress((void**)&wpl, g_wpt_lo);
    cudaGetSymbolAddress((void**)&gao, g_ao);

    const int NE = Bb * Nn * Cc;

    // 1) input & weight conversion
    split_bf16<<<NE / 4 / 256, 256>>>((const float4*)x, xhi, xlo);
    transpose_split<<<dim3(3 * Cc / 32, Cc / 32), dim3(32, 8)>>>(
        Wqkv, wqh, wql, Cc, 3 * Cc);
    transpose_split<<<dim3(Cc / 32, Cc / 32), dim3(32, 8)>>>(
        Wproj, wph, wpl, Cc, Cc);

    // 2) QKV projection (mma.sync bf16, 3-term)
    cudaFuncSetAttribute(mma_gemm<0>, cudaFuncAttributeMaxDynamicSharedMemorySize,
                         GEMM_SMEM);
    mma_gemm<0><<<dim3(3 * Cc / 128, Bb * Nn / 128), 256, GEMM_SMEM>>>(
        xhi, xlo, wqh, wql, bqkv, nullptr, 3 * Cc);

    // 3) Flash attention (fp32)
    cudaFuncSetAttribute(attn_kernel, cudaFuncAttributeMaxDynamicSharedMemorySize,
                         ATTN_SMEM_BYTES);
    attn_kernel<<<dim3(Nn / 128, Hh, Bb), 256, ATTN_SMEM_BYTES>>>(mask);

    // 4) attention-output conversion + output projection
    split_bf16<<<NE / 4 / 256, 256>>>((const float4*)gao, aohi, aolo);
    cudaFuncSetAttribute(mma_gemm<1>, cudaFuncAttributeMaxDynamicSharedMemorySize,
                         GEMM_SMEM);
    mma_gemm<1><<<dim3(Cc / 128, Bb * Nn / 128), 256, GEMM_SMEM>>>(
        aohi, aolo, wph, wpl, bproj, out, Cc);
}